// round 5
// baseline (speedup 1.0000x reference)
#include <cuda_runtime.h>
#include <cstdint>

// ---------------------------------------------------------------------------
// HeavyCompressor round 4 (resubmit after infra failure): mma.sync tf32,
// pre-converted operands, LDS.64 pair-interleaved smem, warp tile 64x64,
// 8 warps, 3-stage LDG-reg pipeline.
//   CTA: 128 rows x 256 cols (c | z). Smem row = 16 tf32 (64B), stored as
//   pairs (k, k+4) in 8B words, chunk index XOR-swizzled by row bit1.
// ---------------------------------------------------------------------------

constexpr int D_     = 2048;
constexpr int HD_    = 128;
constexpr int CTA_M  = 128;
constexpr int KT     = 16;
constexpr int NK     = D_ / KT;                 // 128
constexpr int A_BYTES = CTA_M * 64;             // 8 KB
constexpr int B_BYTES = 256 * 64;               // 16 KB
constexpr int STAGE_BYTES = A_BYTES + B_BYTES;  // 24 KB
constexpr int EPI_STR = 276;                    // floats, 16B-aligned stride
constexpr int SMEM_BYTES = CTA_M * EPI_STR * 4; // 141312 (> 3*STAGE_BYTES)

__device__ __forceinline__ uint32_t f2tf(float f) {
    uint32_t r;
    asm("cvt.rna.tf32.f32 %0, %1;" : "=r"(r) : "f"(f));
    return r;
}
__device__ __forceinline__ void mma_tf32(float* c, uint32_t a0, uint32_t a1,
                                         uint32_t a2, uint32_t a3,
                                         uint32_t b0, uint32_t b1) {
    asm volatile(
        "mma.sync.aligned.m16n8k8.row.col.f32.tf32.tf32.f32 "
        "{%0,%1,%2,%3}, {%4,%5,%6,%7}, {%8,%9}, {%0,%1,%2,%3};"
        : "+f"(c[0]), "+f"(c[1]), "+f"(c[2]), "+f"(c[3])
        : "r"(a0), "r"(a1), "r"(a2), "r"(a3), "r"(b0), "r"(b1));
}

__global__ __launch_bounds__(256, 1)
void heavy_compressor_v4(const float* __restrict__ h,
                         const float* __restrict__ wkv,
                         const float* __restrict__ wz,
                         const float* __restrict__ bias,
                         float* __restrict__ out,
                         int write_second, int out_half)
{
    extern __shared__ char smem[];

    const int tid  = threadIdx.x;
    const int wid  = tid >> 5;
    const int lane = tid & 31;
    const int g    = lane >> 2;
    const int tg   = lane & 3;
    const int warp_m = wid & 1;            // 2 x 64 rows
    const int warp_n = wid >> 1;           // 4 x 64 cols
    const long long row0 = (long long)blockIdx.x * CTA_M;

    float acc[4][8][4];
#pragma unroll
    for (int mi = 0; mi < 4; ++mi)
#pragma unroll
        for (int ni = 0; ni < 8; ++ni)
#pragma unroll
            for (int j = 0; j < 4; ++j) acc[mi][ni][j] = 0.f;

    // ---- loader constants: A half-row per thread, B full row per thread ----
    const int arow = tid >> 1, ah = tid & 1;          // A: row 0..127, k-half
    const int brow = tid;                              // B: row 0..255
    const float* asrc = h + (row0 + arow) * D_ + ah * 8;
    const float* bsrc = (brow < 128) ? (wkv + (long long)brow * D_)
                                     : (wz + (long long)(brow - 128) * D_);
    const int aswz = ((arow >> 1) & 1) * 32;           // 16B-chunk XOR (row bit1)
    const int bswz = ((brow >> 1) & 1) * 32;

    float4 ra0, ra1, rb0, rb1, rb2, rb3;               // staging registers

    auto ldg_stage = [&](int s) {
        const int k0 = s * KT;
        ra0 = *(const float4*)(asrc + k0);
        ra1 = *(const float4*)(asrc + k0 + 4);
        rb0 = *(const float4*)(bsrc + k0);
        rb1 = *(const float4*)(bsrc + k0 + 4);
        rb2 = *(const float4*)(bsrc + k0 + 8);
        rb3 = *(const float4*)(bsrc + k0 + 12);
    };
    auto sts_stage = [&](int buf) {
        char* base = smem + buf * STAGE_BYTES;
        char* arp = base + arow * 64;
        char* brp = base + A_BYTES + brow * 64;
        // A half-row: k = 8*ah + 0..7 -> logical chunks 2*ah, 2*ah+1
        // chunk packs pairs: (q0,q4,q1,q5) then (q2,q6,q3,q7)
        uint4 p0 = make_uint4(f2tf(ra0.x), f2tf(ra1.x), f2tf(ra0.y), f2tf(ra1.y));
        uint4 p1 = make_uint4(f2tf(ra0.z), f2tf(ra1.z), f2tf(ra0.w), f2tf(ra1.w));
        *(uint4*)(arp + ((ah * 32 + 0)  ^ aswz)) = p0;
        *(uint4*)(arp + ((ah * 32 + 16) ^ aswz)) = p1;
        // B full row: k 0..15 -> 4 chunks
        uint4 q0 = make_uint4(f2tf(rb0.x), f2tf(rb1.x), f2tf(rb0.y), f2tf(rb1.y));
        uint4 q1 = make_uint4(f2tf(rb0.z), f2tf(rb1.z), f2tf(rb0.w), f2tf(rb1.w));
        uint4 q2 = make_uint4(f2tf(rb2.x), f2tf(rb3.x), f2tf(rb2.y), f2tf(rb3.y));
        uint4 q3 = make_uint4(f2tf(rb2.z), f2tf(rb3.z), f2tf(rb2.w), f2tf(rb3.w));
        *(uint4*)(brp + (0  ^ bswz)) = q0;
        *(uint4*)(brp + (16 ^ bswz)) = q1;
        *(uint4*)(brp + (32 ^ bswz)) = q2;
        *(uint4*)(brp + (48 ^ bswz)) = q3;
    };

    // fragment-read constants (reader XOR matches writer: row bit1 == g bit1)
    const int fswz = (g & 2) << 1;                       // word-index XOR (bit2)
    const int offk0 = ((tg + 0) ^ fswz) * 8;             // ks=0 byte offset in row
    const int offk1 = ((tg + 4) ^ fswz) * 8;             // ks=1

    // ---- prologue ----
    ldg_stage(0);
    sts_stage(0);
    ldg_stage(1);
    __syncthreads();

    // ---- mainloop ----
#pragma unroll 1
    for (int t = 0; t < NK; ++t) {
        if (t + 1 < NK) sts_stage((t + 1) % 3);
        if (t + 2 < NK) ldg_stage(t + 2);

        const char* cs    = smem + (t % 3) * STAGE_BYTES;
        const char* aBase = cs + (warp_m * 64 + g) * 64;
        const char* bBase = cs + A_BYTES + (warp_n * 64 + g) * 64;

#pragma unroll
        for (int ks = 0; ks < 2; ++ks) {
            const int offk = ks ? offk1 : offk0;
            uint2 av[4][2];
#pragma unroll
            for (int mi = 0; mi < 4; ++mi) {
                av[mi][0] = *(const uint2*)(aBase + mi * 16 * 64 + offk);
                av[mi][1] = *(const uint2*)(aBase + (mi * 16 + 8) * 64 + offk);
            }
            uint2 bv[8];
#pragma unroll
            for (int ni = 0; ni < 8; ++ni)
                bv[ni] = *(const uint2*)(bBase + ni * 8 * 64 + offk);
#pragma unroll
            for (int mi = 0; mi < 4; ++mi)
#pragma unroll
                for (int ni = 0; ni < 8; ++ni)
                    mma_tf32(acc[mi][ni],
                             av[mi][0].x, av[mi][1].x, av[mi][0].y, av[mi][1].y,
                             bv[ni].x, bv[ni].y);
        }
        __syncthreads();
    }

    // ---- epilogue: accums -> smem, windowed softmax-compress ----
    float* epi = (float*)smem;
#pragma unroll
    for (int mi = 0; mi < 4; ++mi)
#pragma unroll
        for (int ni = 0; ni < 8; ++ni) {
            int m0 = warp_m * 64 + mi * 16 + g;
            int n0 = warp_n * 64 + ni * 8 + 2 * tg;
            *(float2*)(epi + m0 * EPI_STR + n0)       = make_float2(acc[mi][ni][0], acc[mi][ni][1]);
            *(float2*)(epi + (m0 + 8) * EPI_STR + n0) = make_float2(acc[mi][ni][2], acc[mi][ni][3]);
        }
    __syncthreads();

    const int win = tid >> 4;            // 16 windows of 8 rows
    const int l16 = tid & 15;
#pragma unroll
    for (int it = 0; it < 2; ++it) {
        const int col0 = l16 * 8 + it * 4;
        float zb[8][4], cc[8][4];
#pragma unroll
        for (int r = 0; r < 8; ++r) {
            const float* rp = epi + (win * 8 + r) * EPI_STR;
            float4 c4 = *(const float4*)(rp + col0);
            float4 z4 = *(const float4*)(rp + HD_ + col0);
            float4 b4 = *(const float4*)(bias + r * HD_ + col0);
            cc[r][0] = c4.x; cc[r][1] = c4.y; cc[r][2] = c4.z; cc[r][3] = c4.w;
            zb[r][0] = z4.x + b4.x; zb[r][1] = z4.y + b4.y;
            zb[r][2] = z4.z + b4.z; zb[r][3] = z4.w + b4.w;
        }
        float res[4];
#pragma unroll
        for (int i = 0; i < 4; ++i) {
            float mx = zb[0][i];
#pragma unroll
            for (int r = 1; r < 8; ++r) mx = fmaxf(mx, zb[r][i]);
            float s = 0.f, a = 0.f;
#pragma unroll
            for (int r = 0; r < 8; ++r) {
                float e = __expf(zb[r][i] - mx);
                s += e;
                a = fmaf(e, cc[r][i], a);
            }
            res[i] = a / s;
        }
        const long long w = (long long)blockIdx.x * 16 + win;
        float4 v = make_float4(res[0], res[1], res[2], res[3]);
        float* dst = out + w * HD_ + col0;
        *(float4*)dst = v;
        if (write_second) *(float4*)(dst + out_half) = v;
    }
}

extern "C" void kernel_launch(void* const* d_in, const int* in_sizes, int n_in,
                              void* d_out, int out_size)
{
    const float* h    = (const float*)d_in[0];
    const float* wkv  = (const float*)d_in[1];
    const float* wz   = (const float*)d_in[2];
    const float* bias = (const float*)d_in[3];

    const int rows = in_sizes[0] / D_;              // 32768
    const int base = (rows / 8) * HD_;              // 524288
    const int write_second = (out_size >= 2 * base) ? 1 : 0;

    cudaFuncSetAttribute(heavy_compressor_v4,
                         cudaFuncAttributeMaxDynamicSharedMemorySize, SMEM_BYTES);
    heavy_compressor_v4<<<rows / CTA_M, 256, SMEM_BYTES>>>(
        h, wkv, wz, bias, (float*)d_out, write_second, base);
}

// round 6
// speedup vs baseline: 1.0681x; 1.0681x over previous
#include <cuda_runtime.h>
#include <cstdint>

// ---------------------------------------------------------------------------
// HeavyCompressor round 6: r3 geometry (512 thr, 16 warps, warp tile 64x32)
// + r4 operand format (pre-converted tf32, pair-interleaved rows, LDS.64).
//   CTA: 128 rows x 256 cols (c | z). Smem row = 16 tf32 (64B) as (k,k+4)
//   pairs; 16B-chunk XOR swizzle by row bit1. 3-stage LDG->cvt->STS ring.
// ---------------------------------------------------------------------------

constexpr int D_     = 2048;
constexpr int HD_    = 128;
constexpr int CTA_M  = 128;
constexpr int KT     = 16;
constexpr int NK     = D_ / KT;                 // 128
constexpr int A_BYTES = CTA_M * 64;             // 8 KB
constexpr int B_BYTES = 256 * 64;               // 16 KB
constexpr int STAGE_BYTES = A_BYTES + B_BYTES;  // 24 KB
constexpr int EPI_STR = 276;                    // floats
constexpr int SMEM_BYTES = CTA_M * EPI_STR * 4; // 141312 (> 3*24KB ring)

__device__ __forceinline__ uint32_t f2tf(float f) {
    uint32_t r;
    asm("cvt.rna.tf32.f32 %0, %1;" : "=r"(r) : "f"(f));
    return r;
}
__device__ __forceinline__ void mma_tf32(float* c, uint32_t a0, uint32_t a1,
                                         uint32_t a2, uint32_t a3,
                                         uint32_t b0, uint32_t b1) {
    asm volatile(
        "mma.sync.aligned.m16n8k8.row.col.f32.tf32.tf32.f32 "
        "{%0,%1,%2,%3}, {%4,%5,%6,%7}, {%8,%9}, {%0,%1,%2,%3};"
        : "+f"(c[0]), "+f"(c[1]), "+f"(c[2]), "+f"(c[3])
        : "r"(a0), "r"(a1), "r"(a2), "r"(a3), "r"(b0), "r"(b1));
}

__global__ __launch_bounds__(512, 1)
void heavy_compressor_v6(const float* __restrict__ h,
                         const float* __restrict__ wkv,
                         const float* __restrict__ wz,
                         const float* __restrict__ bias,
                         float* __restrict__ out,
                         int write_second, int out_half)
{
    extern __shared__ char smem[];

    const int tid  = threadIdx.x;
    const int wid  = tid >> 5;
    const int lane = tid & 31;
    const int g    = lane >> 2;
    const int tg   = lane & 3;
    const int warp_m = wid & 1;            // 2 x 64 rows
    const int warp_n = wid >> 1;           // 8 x 32 cols
    const long long row0 = (long long)blockIdx.x * CTA_M;

    float acc[4][4][4];                    // 64 floats
#pragma unroll
    for (int mi = 0; mi < 4; ++mi)
#pragma unroll
        for (int ni = 0; ni < 4; ++ni)
#pragma unroll
            for (int j = 0; j < 4; ++j) acc[mi][ni][j] = 0.f;

    // ---- loaders: half-row (8 k) per thread ----
    // B: all 512 threads.  brow = tid>>1 (0..255), bh = tid&1
    // A: threads 0..255.   arow = tid>>1 (0..127), ah = tid&1
    const int brow = tid >> 1, bh = tid & 1;
    const float* bsrc = ((brow < 128) ? (wkv + (long long)brow * D_)
                                      : (wz + (long long)(brow - 128) * D_)) + bh * 8;
    const int bswz = ((brow >> 1) & 1) * 32;

    const bool has_a = (tid < 256);
    const int arow = tid >> 1, ah = tid & 1;          // valid when has_a
    const float* asrc = h + (row0 + arow) * D_ + ah * 8;
    const int aswz = ((arow >> 1) & 1) * 32;

    float4 ra0, ra1, rb0, rb1;                         // raw staging

    auto ldg_stage = [&](int s) {
        const int k0 = s * KT;
        rb0 = *(const float4*)(bsrc + k0);
        rb1 = *(const float4*)(bsrc + k0 + 4);
        if (has_a) {
            ra0 = *(const float4*)(asrc + k0);
            ra1 = *(const float4*)(asrc + k0 + 4);
        }
    };
    auto sts_stage = [&](int buf) {
        char* base = smem + buf * STAGE_BYTES;
        // B half-row -> chunks 2*bh, 2*bh+1: pack pairs (q,q+4)
        uint4 q0 = make_uint4(f2tf(rb0.x), f2tf(rb1.x), f2tf(rb0.y), f2tf(rb1.y));
        uint4 q1 = make_uint4(f2tf(rb0.z), f2tf(rb1.z), f2tf(rb0.w), f2tf(rb1.w));
        char* brp = base + A_BYTES + brow * 64;
        *(uint4*)(brp + ((bh * 32 + 0)  ^ bswz)) = q0;
        *(uint4*)(brp + ((bh * 32 + 16) ^ bswz)) = q1;
        if (has_a) {
            uint4 p0 = make_uint4(f2tf(ra0.x), f2tf(ra1.x), f2tf(ra0.y), f2tf(ra1.y));
            uint4 p1 = make_uint4(f2tf(ra0.z), f2tf(ra1.z), f2tf(ra0.w), f2tf(ra1.w));
            char* arp = base + arow * 64;
            *(uint4*)(arp + ((ah * 32 + 0)  ^ aswz)) = p0;
            *(uint4*)(arp + ((ah * 32 + 16) ^ aswz)) = p1;
        }
    };

    // fragment-read constants (reader XOR: row bit1 lives in g bit1)
    const int fswz  = (g & 2) << 1;
    const int offk0 = ((tg + 0) ^ fswz) * 8;
    const int offk1 = ((tg + 4) ^ fswz) * 8;

    // ---- prologue ----
    ldg_stage(0);
    sts_stage(0);
    ldg_stage(1);
    __syncthreads();

    // ---- mainloop ----
#pragma unroll 1
    for (int t = 0; t < NK; ++t) {
        if (t + 1 < NK) sts_stage((t + 1) % 3);
        if (t + 2 < NK) ldg_stage(t + 2);

        const char* cs    = smem + (t % 3) * STAGE_BYTES;
        const char* aBase = cs + (warp_m * 64 + g) * 64;
        const char* bBase = cs + A_BYTES + (warp_n * 32 + g) * 64;

#pragma unroll
        for (int ks = 0; ks < 2; ++ks) {
            const int offk = ks ? offk1 : offk0;
            uint2 av[4][2];
#pragma unroll
            for (int mi = 0; mi < 4; ++mi) {
                av[mi][0] = *(const uint2*)(aBase + mi * 16 * 64 + offk);
                av[mi][1] = *(const uint2*)(aBase + (mi * 16 + 8) * 64 + offk);
            }
            uint2 bv[4];
#pragma unroll
            for (int ni = 0; ni < 4; ++ni)
                bv[ni] = *(const uint2*)(bBase + ni * 8 * 64 + offk);
#pragma unroll
            for (int mi = 0; mi < 4; ++mi)
#pragma unroll
                for (int ni = 0; ni < 4; ++ni)
                    mma_tf32(acc[mi][ni],
                             av[mi][0].x, av[mi][1].x, av[mi][0].y, av[mi][1].y,
                             bv[ni].x, bv[ni].y);
        }
        __syncthreads();
    }

    // ---- epilogue: accums -> smem, windowed softmax-compress ----
    float* epi = (float*)smem;
    __syncthreads();
#pragma unroll
    for (int mi = 0; mi < 4; ++mi)
#pragma unroll
        for (int ni = 0; ni < 4; ++ni) {
            int m0 = warp_m * 64 + mi * 16 + g;
            int n0 = warp_n * 32 + ni * 8 + 2 * tg;
            *(float2*)(epi + m0 * EPI_STR + n0)       = make_float2(acc[mi][ni][0], acc[mi][ni][1]);
            *(float2*)(epi + (m0 + 8) * EPI_STR + n0) = make_float2(acc[mi][ni][2], acc[mi][ni][3]);
        }
    __syncthreads();

    const int win = tid >> 5;            // 16 windows of 8 rows
    float zb[8][4], cc[8][4];
#pragma unroll
    for (int r = 0; r < 8; ++r) {
        const float* rp = epi + (win * 8 + r) * EPI_STR;
        float4 c4 = *(const float4*)(rp + lane * 4);
        float4 z4 = *(const float4*)(rp + HD_ + lane * 4);
        float4 b4 = *(const float4*)(bias + r * HD_ + lane * 4);
        cc[r][0] = c4.x; cc[r][1] = c4.y; cc[r][2] = c4.z; cc[r][3] = c4.w;
        zb[r][0] = z4.x + b4.x; zb[r][1] = z4.y + b4.y;
        zb[r][2] = z4.z + b4.z; zb[r][3] = z4.w + b4.w;
    }
    float res[4];
#pragma unroll
    for (int i = 0; i < 4; ++i) {
        float mx = zb[0][i];
#pragma unroll
        for (int r = 1; r < 8; ++r) mx = fmaxf(mx, zb[r][i]);
        float s = 0.f, a = 0.f;
#pragma unroll
        for (int r = 0; r < 8; ++r) {
            float e = __expf(zb[r][i] - mx);
            s += e;
            a = fmaf(e, cc[r][i], a);
        }
        res[i] = a / s;
    }
    const long long w = (long long)blockIdx.x * 16 + win;
    float4 v = make_float4(res[0], res[1], res[2], res[3]);
    float* dst = out + w * HD_ + lane * 4;
    *(float4*)dst = v;
    if (write_second) *(float4*)(dst + out_half) = v;
}

extern "C" void kernel_launch(void* const* d_in, const int* in_sizes, int n_in,
                              void* d_out, int out_size)
{
    const float* h    = (const float*)d_in[0];
    const float* wkv  = (const float*)d_in[1];
    const float* wz   = (const float*)d_in[2];
    const float* bias = (const float*)d_in[3];

    const int rows = in_sizes[0] / D_;              // 32768
    const int base = (rows / 8) * HD_;              // 524288
    const int write_second = (out_size >= 2 * base) ? 1 : 0;

    cudaFuncSetAttribute(heavy_compressor_v6,
                         cudaFuncAttributeMaxDynamicSharedMemorySize, SMEM_BYTES);
    heavy_compressor_v6<<<rows / CTA_M, 512, SMEM_BYTES>>>(
        h, wkv, wz, bias, (float*)d_out, write_second, base);
}

// round 7
// speedup vs baseline: 1.3324x; 1.2475x over previous
#include <cuda_runtime.h>
#include <cstdint>

// ---------------------------------------------------------------------------
// HeavyCompressor round 7: mma.sync tf32 + ldmatrix fragments (conflict-free
// 16B-cell swizzle), B pre-converted to tf32 in __device__ scratch and
// streamed via cp.async, A converted on the fly (LDG->cvt->STS).
//   CTA: 128 rows x 256 cols (c | z), 512 threads, warp tile 64x32.
//   Smem stage: A 128x16 tf32 (8KB) + B 256x16 tf32 (16KB), rows of four
//   16B cells, cell index ^= (row>>1)&3. 3-stage ring.
// ---------------------------------------------------------------------------

constexpr int D_     = 2048;
constexpr int HD_    = 128;
constexpr int CTA_M  = 128;
constexpr int KT     = 16;
constexpr int NK     = D_ / KT;                 // 128
constexpr int A_BYTES = CTA_M * 64;             // 8 KB
constexpr int B_BYTES = 256 * 64;               // 16 KB
constexpr int STAGE_BYTES = A_BYTES + B_BYTES;  // 24 KB
constexpr int EPI_STR = 276;
constexpr int SMEM_BYTES = CTA_M * EPI_STR * 4; // 141312 (> 3*24KB)

__device__ uint32_t g_wtf32[256 * 2048];        // pre-converted [wkv;wz], tf32 bits

__device__ __forceinline__ uint32_t f2tf(float f) {
    uint32_t r;
    asm("cvt.rna.tf32.f32 %0, %1;" : "=r"(r) : "f"(f));
    return r;
}
__device__ __forceinline__ uint32_t smem_u32(const void* p) {
    uint32_t a;
    asm("{ .reg .u64 t; cvta.to.shared.u64 t, %1; cvt.u32.u64 %0, t; }" : "=r"(a) : "l"(p));
    return a;
}
__device__ __forceinline__ void cp16(uint32_t dst, const void* src) {
    asm volatile("cp.async.cg.shared.global [%0], [%1], 16;" :: "r"(dst), "l"(src) : "memory");
}
__device__ __forceinline__ void ldsm4(uint32_t* r, uint32_t addr) {
    asm volatile("ldmatrix.sync.aligned.m8n8.x4.shared.b16 {%0,%1,%2,%3}, [%4];"
                 : "=r"(r[0]), "=r"(r[1]), "=r"(r[2]), "=r"(r[3]) : "r"(addr));
}
__device__ __forceinline__ void mma_tf32(float* c, uint32_t a0, uint32_t a1,
                                         uint32_t a2, uint32_t a3,
                                         uint32_t b0, uint32_t b1) {
    asm volatile(
        "mma.sync.aligned.m16n8k8.row.col.f32.tf32.tf32.f32 "
        "{%0,%1,%2,%3}, {%4,%5,%6,%7}, {%8,%9}, {%0,%1,%2,%3};"
        : "+f"(c[0]), "+f"(c[1]), "+f"(c[2]), "+f"(c[3])
        : "r"(a0), "r"(a1), "r"(a2), "r"(a3), "r"(b0), "r"(b1));
}

// Pre-convert [wkv; wz] (256 x 2048 fp32) to tf32 bits, row-major.
__global__ void convert_w(const float4* __restrict__ wkv, const float4* __restrict__ wz) {
    int i = blockIdx.x * blockDim.x + threadIdx.x;      // 0..131071 float4s
    int row = i >> 9, c4 = i & 511;
    float4 v = (row < 128) ? wkv[row * 512 + c4] : wz[(row - 128) * 512 + c4];
    ((uint4*)g_wtf32)[i] = make_uint4(f2tf(v.x), f2tf(v.y), f2tf(v.z), f2tf(v.w));
}

__global__ __launch_bounds__(512, 1)
void heavy_compressor_v7(const float* __restrict__ h,
                         const float* __restrict__ bias,
                         float* __restrict__ out,
                         int write_second, int out_half)
{
    extern __shared__ char smem[];
    const uint32_t sbase = smem_u32(smem);

    const int tid  = threadIdx.x;
    const int wid  = tid >> 5;
    const int lane = tid & 31;
    const int g    = lane >> 2;
    const int tg   = lane & 3;
    const int warp_m = wid & 1;            // 2 x 64 rows
    const int warp_n = wid >> 1;           // 8 x 32 cols
    const long long row0 = (long long)blockIdx.x * CTA_M;

    float acc[4][4][4];
#pragma unroll
    for (int mi = 0; mi < 4; ++mi)
#pragma unroll
        for (int ni = 0; ni < 4; ++ni)
#pragma unroll
            for (int j = 0; j < 4; ++j) acc[mi][ni][j] = 0.f;

    // ---- A loader: threads 0..255, half-row (8 k) each ----
    const bool has_a = (tid < 256);
    const int arow = tid >> 1, ah = tid & 1;
    const float* asrc = h + (row0 + arow) * D_ + ah * 8;
    const int sAw = (arow >> 1) & 3;                    // writer cell swizzle
    const int aoff0 = arow * 64 + (((2 * ah + 0) ^ sAw) * 16);
    const int aoff1 = arow * 64 + (((2 * ah + 1) ^ sAw) * 16);
    float4 ra0, ra1;

    auto ldg_a = [&](int s) {
        if (has_a) {
            ra0 = *(const float4*)(asrc + s * KT);
            ra1 = *(const float4*)(asrc + s * KT + 4);
        }
    };
    auto sts_a = [&](int buf) {
        if (has_a) {
            char* base = smem + buf * STAGE_BYTES;
            *(uint4*)(base + aoff0) = make_uint4(f2tf(ra0.x), f2tf(ra0.y), f2tf(ra0.z), f2tf(ra0.w));
            *(uint4*)(base + aoff1) = make_uint4(f2tf(ra1.x), f2tf(ra1.y), f2tf(ra1.z), f2tf(ra1.w));
        }
    };

    // ---- B cp.async: 1024 cells/stage, 2 per thread ----
    const int c0 = tid, c1 = tid + 512;
    const int br0 = c0 >> 2, kc0 = c0 & 3;
    const int br1 = c1 >> 2, kc1 = c1 & 3;
    const uint32_t* bsrc0 = g_wtf32 + br0 * 2048 + kc0 * 4;
    const uint32_t* bsrc1 = g_wtf32 + br1 * 2048 + kc1 * 4;
    const uint32_t bdst0 = A_BYTES + br0 * 64 + ((kc0 ^ ((br0 >> 1) & 3)) * 16);
    const uint32_t bdst1 = A_BYTES + br1 * 64 + ((kc1 ^ ((br1 >> 1) & 3)) * 16);

    auto cp_b = [&](int s) {
        const uint32_t base = sbase + (s % 3) * STAGE_BYTES;
        cp16(base + bdst0, bsrc0 + s * KT);
        cp16(base + bdst1, bsrc1 + s * KT);
    };

    // ---- ldsm lane-constant offsets ----
    const int row16  = (lane & 7) | (((lane >> 3) & 1) << 3);
    const int sA     = (row16 >> 1) & 3;
    const int hiA    = lane >> 4;
    const int offA0  = row16 * 64 + (((0 + hiA) ^ sA) * 16);
    const int offA1  = row16 * 64 + (((2 + hiA) ^ sA) * 16);
    const int brow16 = (lane & 7) | ((lane >> 4) << 3);
    const int sB     = (brow16 >> 1) & 3;
    const int hiB    = (lane >> 3) & 1;
    const int offB0  = brow16 * 64 + (((0 + hiB) ^ sB) * 16);
    const int offB1  = brow16 * 64 + (((2 + hiB) ^ sB) * 16);
    const uint32_t aW = warp_m * 4096;
    const uint32_t bW = A_BYTES + warp_n * 2048;

    // ---- prologue ----
    ldg_a(0);
    sts_a(0);
    ldg_a(1);
    cp_b(0);
    asm volatile("cp.async.commit_group;" ::: "memory");
    cp_b(1);
    asm volatile("cp.async.commit_group;" ::: "memory");

    // ---- mainloop ----
#pragma unroll 1
    for (int t = 0; t < NK; ++t) {
        if (t + 1 < NK) sts_a((t + 1) % 3);
        if (t + 2 < NK) ldg_a(t + 2);

        asm volatile("cp.async.wait_group 1;" ::: "memory");
        __syncthreads();

        if (t + 2 < NK) cp_b(t + 2);
        asm volatile("cp.async.commit_group;" ::: "memory");

        const uint32_t cs = sbase + (t % 3) * STAGE_BYTES;
#pragma unroll
        for (int ks = 0; ks < 2; ++ks) {
            const int oa = ks ? offA1 : offA0;
            const int ob = ks ? offB1 : offB0;
            uint32_t a[4][4], b[2][4];
#pragma unroll
            for (int mi = 0; mi < 4; ++mi)
                ldsm4(a[mi], cs + aW + mi * 1024 + oa);
#pragma unroll
            for (int np = 0; np < 2; ++np)
                ldsm4(b[np], cs + bW + np * 1024 + ob);
#pragma unroll
            for (int mi = 0; mi < 4; ++mi)
#pragma unroll
                for (int ni = 0; ni < 4; ++ni)
                    mma_tf32(acc[mi][ni],
                             a[mi][0], a[mi][1], a[mi][2], a[mi][3],
                             b[ni >> 1][(ni & 1) * 2], b[ni >> 1][(ni & 1) * 2 + 1]);
        }
    }

    // ---- epilogue: accums -> smem, windowed softmax-compress ----
    float* epi = (float*)smem;
    __syncthreads();
#pragma unroll
    for (int mi = 0; mi < 4; ++mi)
#pragma unroll
        for (int ni = 0; ni < 4; ++ni) {
            int m0 = warp_m * 64 + mi * 16 + g;
            int n0 = warp_n * 32 + ni * 8 + 2 * tg;
            *(float2*)(epi + m0 * EPI_STR + n0)       = make_float2(acc[mi][ni][0], acc[mi][ni][1]);
            *(float2*)(epi + (m0 + 8) * EPI_STR + n0) = make_float2(acc[mi][ni][2], acc[mi][ni][3]);
        }
    __syncthreads();

    const int win = tid >> 5;            // 16 windows of 8 rows
    float zb[8][4], cc[8][4];
#pragma unroll
    for (int r = 0; r < 8; ++r) {
        const float* rp = epi + (win * 8 + r) * EPI_STR;
        float4 c4 = *(const float4*)(rp + lane * 4);
        float4 z4 = *(const float4*)(rp + HD_ + lane * 4);
        float4 b4 = *(const float4*)(bias + r * HD_ + lane * 4);
        cc[r][0] = c4.x; cc[r][1] = c4.y; cc[r][2] = c4.z; cc[r][3] = c4.w;
        zb[r][0] = z4.x + b4.x; zb[r][1] = z4.y + b4.y;
        zb[r][2] = z4.z + b4.z; zb[r][3] = z4.w + b4.w;
    }
    float res[4];
#pragma unroll
    for (int i = 0; i < 4; ++i) {
        float mx = zb[0][i];
#pragma unroll
        for (int r = 1; r < 8; ++r) mx = fmaxf(mx, zb[r][i]);
        float s = 0.f, a = 0.f;
#pragma unroll
        for (int r = 0; r < 8; ++r) {
            float e = __expf(zb[r][i] - mx);
            s += e;
            a = fmaf(e, cc[r][i], a);
        }
        res[i] = a / s;
    }
    const long long w = (long long)blockIdx.x * 16 + win;
    float4 v = make_float4(res[0], res[1], res[2], res[3]);
    float* dst = out + w * HD_ + lane * 4;
    *(float4*)dst = v;
    if (write_second) *(float4*)(dst + out_half) = v;
}

extern "C" void kernel_launch(void* const* d_in, const int* in_sizes, int n_in,
                              void* d_out, int out_size)
{
    const float* h    = (const float*)d_in[0];
    const float* wkv  = (const float*)d_in[1];
    const float* wz   = (const float*)d_in[2];
    const float* bias = (const float*)d_in[3];

    const int rows = in_sizes[0] / D_;              // 32768
    const int base = (rows / 8) * HD_;              // 524288
    const int write_second = (out_size >= 2 * base) ? 1 : 0;

    convert_w<<<512, 256>>>((const float4*)wkv, (const float4*)wz);

    cudaFuncSetAttribute(heavy_compressor_v7,
                         cudaFuncAttributeMaxDynamicSharedMemorySize, SMEM_BYTES);
    heavy_compressor_v7<<<rows / CTA_M, 512, SMEM_BYTES>>>(
        h, bias, (float*)d_out, write_second, base);
}

// round 8
// speedup vs baseline: 1.7388x; 1.3050x over previous
#include <cuda_runtime.h>
#include <cstdint>

// ---------------------------------------------------------------------------
// HeavyCompressor round 8: v7 (ldsm + tf32 mma, pre-converted B) with KT=32
// to halve per-tile barrier/fixed overhead. Stage rows = 32 tf32 = 128B =
// 8 x 16B cells, swizzle cell ^= (row & 7). 3-stage ring (144 KB).
//   CTA: 128 rows x 256 cols (c | z), 512 threads, warp tile 64x32.
// ---------------------------------------------------------------------------

constexpr int D_     = 2048;
constexpr int HD_    = 128;
constexpr int CTA_M  = 128;
constexpr int KT     = 32;
constexpr int NK     = D_ / KT;                 // 64
constexpr int A_BYTES = CTA_M * 128;            // 16 KB
constexpr int B_BYTES = 256 * 128;              // 32 KB
constexpr int STAGE_BYTES = A_BYTES + B_BYTES;  // 48 KB
constexpr int EPI_STR = 276;
constexpr int SMEM_BYTES = 3 * STAGE_BYTES;     // 147456 (> 138KB epilogue)

__device__ uint32_t g_wtf32[256 * 2048];        // pre-converted [wkv;wz] tf32 bits

__device__ __forceinline__ uint32_t f2tf(float f) {
    uint32_t r;
    asm("cvt.rna.tf32.f32 %0, %1;" : "=r"(r) : "f"(f));
    return r;
}
__device__ __forceinline__ uint32_t smem_u32(const void* p) {
    uint32_t a;
    asm("{ .reg .u64 t; cvta.to.shared.u64 t, %1; cvt.u32.u64 %0, t; }" : "=r"(a) : "l"(p));
    return a;
}
__device__ __forceinline__ void cp16(uint32_t dst, const void* src) {
    asm volatile("cp.async.cg.shared.global [%0], [%1], 16;" :: "r"(dst), "l"(src) : "memory");
}
__device__ __forceinline__ void ldsm4(uint32_t* r, uint32_t addr) {
    asm volatile("ldmatrix.sync.aligned.m8n8.x4.shared.b16 {%0,%1,%2,%3}, [%4];"
                 : "=r"(r[0]), "=r"(r[1]), "=r"(r[2]), "=r"(r[3]) : "r"(addr));
}
__device__ __forceinline__ void mma_tf32(float* c, uint32_t a0, uint32_t a1,
                                         uint32_t a2, uint32_t a3,
                                         uint32_t b0, uint32_t b1) {
    asm volatile(
        "mma.sync.aligned.m16n8k8.row.col.f32.tf32.tf32.f32 "
        "{%0,%1,%2,%3}, {%4,%5,%6,%7}, {%8,%9}, {%0,%1,%2,%3};"
        : "+f"(c[0]), "+f"(c[1]), "+f"(c[2]), "+f"(c[3])
        : "r"(a0), "r"(a1), "r"(a2), "r"(a3), "r"(b0), "r"(b1));
}

__global__ void convert_w(const float4* __restrict__ wkv, const float4* __restrict__ wz) {
    int i = blockIdx.x * blockDim.x + threadIdx.x;      // 0..131071 float4s
    int row = i >> 9, c4 = i & 511;
    float4 v = (row < 128) ? wkv[row * 512 + c4] : wz[(row - 128) * 512 + c4];
    ((uint4*)g_wtf32)[i] = make_uint4(f2tf(v.x), f2tf(v.y), f2tf(v.z), f2tf(v.w));
}

__global__ __launch_bounds__(512, 1)
void heavy_compressor_v8(const float* __restrict__ h,
                         const float* __restrict__ bias,
                         float* __restrict__ out,
                         int write_second, int out_half)
{
    extern __shared__ char smem[];
    const uint32_t sbase = smem_u32(smem);

    const int tid  = threadIdx.x;
    const int wid  = tid >> 5;
    const int lane = tid & 31;
    const int g    = lane >> 2;
    const int tg   = lane & 3;
    const int warp_m = wid & 1;            // 2 x 64 rows
    const int warp_n = wid >> 1;           // 8 x 32 cols
    const long long row0 = (long long)blockIdx.x * CTA_M;

    float acc[4][4][4];
#pragma unroll
    for (int mi = 0; mi < 4; ++mi)
#pragma unroll
        for (int ni = 0; ni < 4; ++ni)
#pragma unroll
            for (int j = 0; j < 4; ++j) acc[mi][ni][j] = 0.f;

    // ---- A loader: 512 threads, 8 k (2 float4) each ----
    const int arow = tid >> 2, aq = tid & 3;            // row 0..127, k-quarter
    const float* asrc = h + (row0 + arow) * D_ + aq * 8;
    const int aswz = arow & 7;
    const int aoff0 = arow * 128 + (((2 * aq + 0) ^ aswz) * 16);
    const int aoff1 = arow * 128 + (((2 * aq + 1) ^ aswz) * 16);
    float4 ra0, ra1;

    auto ldg_a = [&](int s) {
        ra0 = *(const float4*)(asrc + s * KT);
        ra1 = *(const float4*)(asrc + s * KT + 4);
    };
    auto sts_a = [&](int buf) {
        char* base = smem + buf * STAGE_BYTES;
        *(uint4*)(base + aoff0) = make_uint4(f2tf(ra0.x), f2tf(ra0.y), f2tf(ra0.z), f2tf(ra0.w));
        *(uint4*)(base + aoff1) = make_uint4(f2tf(ra1.x), f2tf(ra1.y), f2tf(ra1.z), f2tf(ra1.w));
    };

    // ---- B cp.async: 2048 cells/stage, 4 per thread ----
    uint32_t bdst[4];
    const uint32_t* bsrc[4];
#pragma unroll
    for (int i = 0; i < 4; ++i) {
        int idx = i * 512 + tid;
        int brow = idx >> 3, kc = idx & 7;
        bsrc[i] = g_wtf32 + brow * 2048 + kc * 4;
        bdst[i] = A_BYTES + brow * 128 + ((kc ^ (brow & 7)) * 16);
    }
    auto cp_b = [&](int s) {
        const uint32_t base = sbase + (s % 3) * STAGE_BYTES;
#pragma unroll
        for (int i = 0; i < 4; ++i) cp16(base + bdst[i], bsrc[i] + s * KT);
    };

    // ---- ldsm lane-constant offsets (cell ^= row&7; row low bits = lane&7) ----
    const int row16  = (lane & 7) | (((lane >> 3) & 1) << 3);
    const int hiA    = lane >> 4;
    const int brow16 = (lane & 7) | ((lane >> 4) << 3);
    const int hiB    = (lane >> 3) & 1;
    const int l7     = lane & 7;
    int offA[4], offB[4];
#pragma unroll
    for (int ks = 0; ks < 4; ++ks) {
        offA[ks] = row16  * 128 + (((2 * ks + hiA) ^ l7) * 16);
        offB[ks] = brow16 * 128 + (((2 * ks + hiB) ^ l7) * 16);
    }
    const uint32_t aW = warp_m * 8192;                  // 64 rows * 128B
    const uint32_t bW = A_BYTES + warp_n * 4096;        // 32 rows * 128B

    // ---- prologue ----
    ldg_a(0);
    sts_a(0);
    ldg_a(1);
    cp_b(0);
    asm volatile("cp.async.commit_group;" ::: "memory");
    cp_b(1);
    asm volatile("cp.async.commit_group;" ::: "memory");

    // ---- mainloop ----
#pragma unroll 1
    for (int t = 0; t < NK; ++t) {
        if (t + 1 < NK) sts_a((t + 1) % 3);
        if (t + 2 < NK) ldg_a(t + 2);

        asm volatile("cp.async.wait_group 1;" ::: "memory");
        __syncthreads();

        if (t + 2 < NK) cp_b(t + 2);
        asm volatile("cp.async.commit_group;" ::: "memory");

        const uint32_t cs = sbase + (t % 3) * STAGE_BYTES;
#pragma unroll
        for (int ks = 0; ks < 4; ++ks) {
            uint32_t a[4][4], b[2][4];
#pragma unroll
            for (int mi = 0; mi < 4; ++mi)
                ldsm4(a[mi], cs + aW + mi * 2048 + offA[ks]);
#pragma unroll
            for (int np = 0; np < 2; ++np)
                ldsm4(b[np], cs + bW + np * 2048 + offB[ks]);
#pragma unroll
            for (int mi = 0; mi < 4; ++mi)
#pragma unroll
                for (int ni = 0; ni < 4; ++ni)
                    mma_tf32(acc[mi][ni],
                             a[mi][0], a[mi][1], a[mi][2], a[mi][3],
                             b[ni >> 1][(ni & 1) * 2], b[ni >> 1][(ni & 1) * 2 + 1]);
        }
    }

    // ---- epilogue: accums -> smem, windowed softmax-compress ----
    float* epi = (float*)smem;
    __syncthreads();
#pragma unroll
    for (int mi = 0; mi < 4; ++mi)
#pragma unroll
        for (int ni = 0; ni < 4; ++ni) {
            int m0 = warp_m * 64 + mi * 16 + g;
            int n0 = warp_n * 32 + ni * 8 + 2 * tg;
            *(float2*)(epi + m0 * EPI_STR + n0)       = make_float2(acc[mi][ni][0], acc[mi][ni][1]);
            *(float2*)(epi + (m0 + 8) * EPI_STR + n0) = make_float2(acc[mi][ni][2], acc[mi][ni][3]);
        }
    __syncthreads();

    const int win = tid >> 5;            // 16 windows of 8 rows
    float zb[8][4], cc[8][4];
#pragma unroll
    for (int r = 0; r < 8; ++r) {
        const float* rp = epi + (win * 8 + r) * EPI_STR;
        float4 c4 = *(const float4*)(rp + lane * 4);
        float4 z4 = *(const float4*)(rp + HD_ + lane * 4);
        float4 b4 = *(const float4*)(bias + r * HD_ + lane * 4);
        cc[r][0] = c4.x; cc[r][1] = c4.y; cc[r][2] = c4.z; cc[r][3] = c4.w;
        zb[r][0] = z4.x + b4.x; zb[r][1] = z4.y + b4.y;
        zb[r][2] = z4.z + b4.z; zb[r][3] = z4.w + b4.w;
    }
    float res[4];
#pragma unroll
    for (int i = 0; i < 4; ++i) {
        float mx = zb[0][i];
#pragma unroll
        for (int r = 1; r < 8; ++r) mx = fmaxf(mx, zb[r][i]);
        float s = 0.f, a = 0.f;
#pragma unroll
        for (int r = 0; r < 8; ++r) {
            float e = __expf(zb[r][i] - mx);
            s += e;
            a = fmaf(e, cc[r][i], a);
        }
        res[i] = a / s;
    }
    const long long w = (long long)blockIdx.x * 16 + win;
    float4 v = make_float4(res[0], res[1], res[2], res[3]);
    float* dst = out + w * HD_ + lane * 4;
    *(float4*)dst = v;
    if (write_second) *(float4*)(dst + out_half) = v;
}

extern "C" void kernel_launch(void* const* d_in, const int* in_sizes, int n_in,
                              void* d_out, int out_size)
{
    const float* h    = (const float*)d_in[0];
    const float* wkv  = (const float*)d_in[1];
    const float* wz   = (const float*)d_in[2];
    const float* bias = (const float*)d_in[3];

    const int rows = in_sizes[0] / D_;              // 32768
    const int base = (rows / 8) * HD_;              // 524288
    const int write_second = (out_size >= 2 * base) ? 1 : 0;

    convert_w<<<512, 256>>>((const float4*)wkv, (const float4*)wz);

    cudaFuncSetAttribute(heavy_compressor_v8,
                         cudaFuncAttributeMaxDynamicSharedMemorySize, SMEM_BYTES);
    heavy_compressor_v8<<<rows / CTA_M, 512, SMEM_BYTES>>>(
        h, bias, (float*)d_out, write_second, base);
}